// round 13
// baseline (speedup 1.0000x reference)
#include <cuda_runtime.h>
#include <cuda_bf16.h>
#include <cuda_fp16.h>
#include <math.h>
#include <cstdint>

#define H 64
#define NN 12000
#define NE 50000
#define EHD 128          // 2H
#define QC 8192          // H * 2H
#define NNP 12032        // NN padded to 128
#define NEP 50048        // NE padded to 128
#define KS 192           // split-K (hi|hi|lo)
#define STRQ 200         // smem row stride (bf16) for eh_mma
#define STR2 72          // smem row stride (bf16) for q_mma chunks
#define QSLOT 72         // halves per thread slot in msg staging

// ---------------- scratch (device globals; allocation-free) ----------------
__device__ __align__(16) float g_eh[NE * EHD];          // 25.6 MB
__device__ __align__(16) __half g_q[(size_t)NN * QC];   // 196 MB (fp16)
__device__ float g_agg[NN * H];
__device__ float g_WihT[64 * 192];
__device__ float g_WhhT[64 * 192];
__device__ __align__(16) __nv_bfloat16 g_Asplit[NNP * KS];   // node  hi|hi|lo
__device__ __align__(16) __nv_bfloat16 g_Bsplit[QC * KS];    // W2^T  hi|lo|hi
__device__ __align__(16) __nv_bfloat16 g_Esplit[NEP * KS];   // edge  hi|hi|lo
__device__ __align__(16) __nv_bfloat16 g_W1split[128 * KS];  // W1    hi|lo|hi
__device__ int g_cnt[NN];
__device__ int g_off[NN + 1];
__device__ int g_cur[NN];
__device__ int g_elist[NE];

__device__ __forceinline__ uint32_t smem_to_u32(const void* p) {
    uint32_t a;
    asm("{ .reg .u64 t; cvta.to.shared.u64 t, %1; cvt.u32.u64 %0, t; }" : "=r"(a) : "l"(p));
    return a;
}
__device__ __forceinline__ void cp16(void* s, const void* g) {
    uint32_t sa = smem_to_u32(s);
    asm volatile("cp.async.cg.shared.global [%0], [%1], 16;" :: "r"(sa), "l"(g));
}
__device__ __forceinline__ void cp16a(uint32_t sa, const void* g) {
    asm volatile("cp.async.cg.shared.global [%0], [%1], 16;" :: "r"(sa), "l"(g));
}
__device__ __forceinline__ uint32_t pack_bf2(float a, float b) {
    __nv_bfloat162 v = __floats2bfloat162_rn(a, b);
    return *reinterpret_cast<uint32_t*>(&v);
}

// ---------------- CSR zero (independent of prep) ----------------
__global__ void zero_cnt_kernel() {
    int i = blockIdx.x * blockDim.x + threadIdx.x;
    if (i < NN) g_cnt[i] = 0;
}

// ---------------- PREP (fused zero-agg + transposes + bf16 splits) ----------
__global__ __launch_bounds__(256) void prep_kernel(const float* __restrict__ node,
                                                   const float* __restrict__ edge,
                                                   const float* __restrict__ W1,
                                                   const float* __restrict__ W2,
                                                   const float* __restrict__ Wih,
                                                   const float* __restrict__ Whh) {
    __shared__ float Ws[64 * 128];
    int b = blockIdx.x;
    int t = threadIdx.x;
    if (b < 64) {
        int n0 = b * 128;
        for (int j = t; j < 8192; j += 256) {
            int k = j >> 7, n = j & 127;
            Ws[k * 128 + n] = W2[(size_t)k * QC + n0 + n];
        }
        __syncthreads();
        for (int j = t; j < 8192; j += 256) {
            int n = j >> 6, k = j & 63;
            float x = Ws[k * 128 + n];
            __nv_bfloat16 hi = __float2bfloat16(x);
            __nv_bfloat16 lo = __float2bfloat16(x - __bfloat162float(hi));
            size_t base = (size_t)(n0 + n) * KS;
            g_Bsplit[base + k] = hi;
            g_Bsplit[base + 64 + k] = lo;
            g_Bsplit[base + 128 + k] = hi;
        }
        return;
    }
    int i0 = (b - 64) * 256 + t;
    int stride = (gridDim.x - 64) * 256;
    for (int j = i0; j < NN * H; j += stride) g_agg[j] = 0.f;
    for (int j = i0; j < 192 * 64; j += stride) {
        int r = j >> 6, h = j & 63;
        g_WihT[h * 192 + r] = Wih[j];
        g_WhhT[h * 192 + r] = Whh[j];
    }
    for (int j = i0; j < 128 * 64; j += stride) {
        int n = j >> 6, k = j & 63;
        float x = W1[j];
        __nv_bfloat16 hi = __float2bfloat16(x);
        __nv_bfloat16 lo = __float2bfloat16(x - __bfloat162float(hi));
        g_W1split[n * KS + k] = hi;
        g_W1split[n * KS + 64 + k] = lo;
        g_W1split[n * KS + 128 + k] = hi;
    }
    for (int j = i0; j < NNP * 32; j += stride) {
        int n = j >> 5, hp = j & 31;
        float2 x = (n < NN) ? reinterpret_cast<const float2*>(node)[n * 32 + hp]
                            : make_float2(0.f, 0.f);
        float h0 = __bfloat162float(__float2bfloat16(x.x));
        float h1 = __bfloat162float(__float2bfloat16(x.y));
        uint32_t hi2 = pack_bf2(x.x, x.y);
        uint32_t lo2 = pack_bf2(x.x - h0, x.y - h1);
        uint32_t* base = reinterpret_cast<uint32_t*>(g_Asplit + (size_t)n * KS);
        base[hp] = hi2;
        base[32 + hp] = hi2;
        base[64 + hp] = lo2;
    }
    for (int j = i0; j < NEP * 32; j += stride) {
        int n = j >> 5, hp = j & 31;
        float2 x = (n < NE) ? reinterpret_cast<const float2*>(edge)[n * 32 + hp]
                            : make_float2(0.f, 0.f);
        float h0 = __bfloat162float(__float2bfloat16(x.x));
        float h1 = __bfloat162float(__float2bfloat16(x.y));
        uint32_t hi2 = pack_bf2(x.x, x.y);
        uint32_t lo2 = pack_bf2(x.x - h0, x.y - h1);
        uint32_t* base = reinterpret_cast<uint32_t*>(g_Esplit + (size_t)n * KS);
        base[hp] = hi2;
        base[32 + hp] = hi2;
        base[64 + hp] = lo2;
    }
}

// ---------------- CSR by src ----------------
__global__ void count_kernel(const int* __restrict__ src) {
    int e = blockIdx.x * blockDim.x + threadIdx.x;
    if (e < NE) atomicAdd(&g_cnt[src[e]], 1);
}

__global__ void scan_kernel() {
    __shared__ int sm[1024];
    int tid = threadIdx.x;
    const int C = 12;
    int base = tid * C;
    int loc[C];
    int s = 0;
#pragma unroll
    for (int i = 0; i < C; i++) {
        int v = (base + i < NN) ? g_cnt[base + i] : 0;
        loc[i] = s;
        s += v;
    }
    sm[tid] = s;
    __syncthreads();
    for (int d = 1; d < 1024; d <<= 1) {
        int v = (tid >= d) ? sm[tid - d] : 0;
        __syncthreads();
        if (tid >= d) sm[tid] += v;
        __syncthreads();
    }
    int ex = sm[tid] - s;
#pragma unroll
    for (int i = 0; i < C; i++) {
        if (base + i < NN) {
            g_off[base + i] = ex + loc[i];
            g_cur[base + i] = ex + loc[i];
        }
    }
    if (tid == 1023) g_off[NN] = sm[1023];
}

__global__ void scatter_kernel(const int* __restrict__ src) {
    int e = blockIdx.x * blockDim.x + threadIdx.x;
    if (e < NE) {
        int p = atomicAdd(&g_cur[src[e]], 1);
        g_elist[p] = e;
    }
}

// ---------------- eh = relu(edge @ W1.T + b1) on mma.sync ----------------
__global__ __launch_bounds__(256, 2) void eh_mma(const float* __restrict__ b1) {
    extern __shared__ __nv_bfloat16 sme[];
    __nv_bfloat16* As = sme;               // [128][STRQ]
    __nv_bfloat16* Bs = sme + 128 * STRQ;  // [128][STRQ]
    int m0 = blockIdx.x * 128;
    int tid = threadIdx.x;

    for (int i = tid; i < 3072; i += 256) {
        int r = i / 24, c = i % 24;
        *reinterpret_cast<uint4*>(As + r * STRQ + c * 8) =
            reinterpret_cast<const uint4*>(g_Esplit + (size_t)(m0 + r) * KS)[c];
        *reinterpret_cast<uint4*>(Bs + r * STRQ + c * 8) =
            reinterpret_cast<const uint4*>(g_W1split + (size_t)r * KS)[c];
    }
    __syncthreads();

    int w = tid >> 5, lane = tid & 31;
    int wm = (w & 3) * 32, wn = (w >> 2) * 64;
    int g = lane >> 3;
    int arow = (lane & 7) + (g & 1) * 8, aka = (g >> 1) * 8;
    int brow = (lane & 7) + (g >> 1) * 8, bka = (g & 1) * 8;

    float acc[2][8][4];
#pragma unroll
    for (int im = 0; im < 2; im++)
#pragma unroll
        for (int jn = 0; jn < 8; jn++)
#pragma unroll
            for (int c = 0; c < 4; c++) acc[im][jn][c] = 0.f;

#pragma unroll
    for (int kk = 0; kk < 12; kk++) {
        int k0 = kk * 16;
        uint32_t a[2][4];
#pragma unroll
        for (int im = 0; im < 2; im++) {
            uint32_t addr = smem_to_u32(As + (wm + im * 16 + arow) * STRQ + k0 + aka);
            asm volatile("ldmatrix.sync.aligned.m8n8.x4.shared.b16 {%0,%1,%2,%3}, [%4];"
                         : "=r"(a[im][0]), "=r"(a[im][1]), "=r"(a[im][2]), "=r"(a[im][3])
                         : "r"(addr));
        }
#pragma unroll
        for (int jb = 0; jb < 4; jb++) {
            uint32_t b0, b1r, b2, b3;
            uint32_t addr = smem_to_u32(Bs + (wn + jb * 16 + brow) * STRQ + k0 + bka);
            asm volatile("ldmatrix.sync.aligned.m8n8.x4.shared.b16 {%0,%1,%2,%3}, [%4];"
                         : "=r"(b0), "=r"(b1r), "=r"(b2), "=r"(b3) : "r"(addr));
#pragma unroll
            for (int im = 0; im < 2; im++) {
                asm volatile(
                    "mma.sync.aligned.m16n8k16.row.col.f32.bf16.bf16.f32 "
                    "{%0,%1,%2,%3}, {%4,%5,%6,%7}, {%8,%9}, {%0,%1,%2,%3};"
                    : "+f"(acc[im][jb * 2][0]), "+f"(acc[im][jb * 2][1]),
                      "+f"(acc[im][jb * 2][2]), "+f"(acc[im][jb * 2][3])
                    : "r"(a[im][0]), "r"(a[im][1]), "r"(a[im][2]), "r"(a[im][3]),
                      "r"(b0), "r"(b1r));
                asm volatile(
                    "mma.sync.aligned.m16n8k16.row.col.f32.bf16.bf16.f32 "
                    "{%0,%1,%2,%3}, {%4,%5,%6,%7}, {%8,%9}, {%0,%1,%2,%3};"
                    : "+f"(acc[im][jb * 2 + 1][0]), "+f"(acc[im][jb * 2 + 1][1]),
                      "+f"(acc[im][jb * 2 + 1][2]), "+f"(acc[im][jb * 2 + 1][3])
                    : "r"(a[im][0]), "r"(a[im][1]), "r"(a[im][2]), "r"(a[im][3]),
                      "r"(b2), "r"(b3));
            }
        }
    }

#pragma unroll
    for (int im = 0; im < 2; im++) {
        int m = m0 + wm + im * 16 + (lane >> 2);
#pragma unroll
        for (int jn = 0; jn < 8; jn++) {
            int c = wn + jn * 8 + (lane & 3) * 2;
            float bb0 = b1[c], bb1 = b1[c + 1];
            if (m < NE)
                *reinterpret_cast<float2*>(&g_eh[(size_t)m * EHD + c]) =
                    make_float2(fmaxf(acc[im][jn][0] + bb0, 0.f),
                                fmaxf(acc[im][jn][1] + bb1, 0.f));
            if (m + 8 < NE)
                *reinterpret_cast<float2*>(&g_eh[(size_t)(m + 8) * EHD + c]) =
                    make_float2(fmaxf(acc[im][jn][2] + bb0, 0.f),
                                fmaxf(acc[im][jn][3] + bb1, 0.f));
        }
    }
}

// ---------------- q GEMM: 4 warps, 64x64 warp tiles, cp.async pipeline ------
__global__ __launch_bounds__(128) void q_mma() {
    extern __shared__ __nv_bfloat16 smq[];
    __nv_bfloat16* As = smq;               // [2][128][STR2]
    __nv_bfloat16* Bs = smq + 2 * 128 * STR2;
    int n0 = blockIdx.x * 128, m0 = blockIdx.y * 128;
    int tid = threadIdx.x;

    int w = tid >> 5, lane = tid & 31;
    int wm = (w & 1) * 64, wn = (w >> 1) * 64;
    int g = lane >> 3;
    int arow = (lane & 7) + (g & 1) * 8, aka = (g >> 1) * 8;
    int brow = (lane & 7) + (g >> 1) * 8, bka = (g & 1) * 8;

    float acc[4][8][4];
#pragma unroll
    for (int im = 0; im < 4; im++)
#pragma unroll
        for (int jn = 0; jn < 8; jn++)
#pragma unroll
            for (int c = 0; c < 4; c++) acc[im][jn][c] = 0.f;

#define STAGE(c) do { \
        int _buf = (c) & 1; \
        __nv_bfloat16* _Ad = As + _buf * 128 * STR2; \
        __nv_bfloat16* _Bd = Bs + _buf * 128 * STR2; \
        const __nv_bfloat16* _Ag = g_Asplit + (size_t)m0 * KS + (c) * 64; \
        const __nv_bfloat16* _Bg = g_Bsplit + (size_t)n0 * KS + (c) * 64; \
        _Pragma("unroll") \
        for (int _i = 0; _i < 8; _i++) { \
            int _idx = tid + _i * 128; \
            int _r = _idx >> 3, _j = _idx & 7; \
            cp16(_Ad + _r * STR2 + _j * 8, _Ag + (size_t)_r * KS + _j * 8); \
            cp16(_Bd + _r * STR2 + _j * 8, _Bg + (size_t)_r * KS + _j * 8); \
        } \
        asm volatile("cp.async.commit_group;"); \
    } while (0)

    STAGE(0);
#pragma unroll
    for (int c = 0; c < 3; c++) {
        if (c + 1 < 3) STAGE(c + 1);
        if (c + 1 < 3) asm volatile("cp.async.wait_group 1;");
        else           asm volatile("cp.async.wait_group 0;");
        __syncthreads();
        const __nv_bfloat16* Ab = As + (c & 1) * 128 * STR2;
        const __nv_bfloat16* Bb = Bs + (c & 1) * 128 * STR2;
#pragma unroll
        for (int ks = 0; ks < 4; ks++) {
            int k0 = ks * 16;
            uint32_t a[4][4];
#pragma unroll
            for (int im = 0; im < 4; im++) {
                uint32_t addr = smem_to_u32(Ab + (wm + im * 16 + arow) * STR2 + k0 + aka);
                asm volatile("ldmatrix.sync.aligned.m8n8.x4.shared.b16 {%0,%1,%2,%3}, [%4];"
                             : "=r"(a[im][0]), "=r"(a[im][1]), "=r"(a[im][2]), "=r"(a[im][3])
                             : "r"(addr));
            }
#pragma unroll
            for (int jb = 0; jb < 4; jb++) {
                uint32_t b0, b1, b2, b3;
                uint32_t addr = smem_to_u32(Bb + (wn + jb * 16 + brow) * STR2 + k0 + bka);
                asm volatile("ldmatrix.sync.aligned.m8n8.x4.shared.b16 {%0,%1,%2,%3}, [%4];"
                             : "=r"(b0), "=r"(b1), "=r"(b2), "=r"(b3) : "r"(addr));
#pragma unroll
                for (int im = 0; im < 4; im++) {
                    asm volatile(
                        "mma.sync.aligned.m16n8k16.row.col.f32.bf16.bf16.f32 "
                        "{%0,%1,%2,%3}, {%4,%5,%6,%7}, {%8,%9}, {%0,%1,%2,%3};"
                        : "+f"(acc[im][jb * 2][0]), "+f"(acc[im][jb * 2][1]),
                          "+f"(acc[im][jb * 2][2]), "+f"(acc[im][jb * 2][3])
                        : "r"(a[im][0]), "r"(a[im][1]), "r"(a[im][2]), "r"(a[im][3]),
                          "r"(b0), "r"(b1));
                    asm volatile(
                        "mma.sync.aligned.m16n8k16.row.col.f32.bf16.bf16.f32 "
                        "{%0,%1,%2,%3}, {%4,%5,%6,%7}, {%8,%9}, {%0,%1,%2,%3};"
                        : "+f"(acc[im][jb * 2 + 1][0]), "+f"(acc[im][jb * 2 + 1][1]),
                          "+f"(acc[im][jb * 2 + 1][2]), "+f"(acc[im][jb * 2 + 1][3])
                        : "r"(a[im][0]), "r"(a[im][1]), "r"(a[im][2]), "r"(a[im][3]),
                          "r"(b2), "r"(b3));
                }
            }
        }
        __syncthreads();
    }
#undef STAGE

#pragma unroll
    for (int im = 0; im < 4; im++) {
        int m = m0 + wm + im * 16 + (lane >> 2);
#pragma unroll
        for (int jn = 0; jn < 8; jn++) {
            int c = n0 + wn + jn * 8 + (lane & 3) * 2;
            if (m < NN)
                *reinterpret_cast<__half2*>(&g_q[(size_t)m * QC + c]) =
                    __floats2half2_rn(acc[im][jn][0], acc[im][jn][1]);
            if (m + 8 < NN)
                *reinterpret_cast<__half2*>(&g_q[(size_t)(m + 8) * QC + c]) =
                    __floats2half2_rn(acc[im][jn][2], acc[im][jn][3]);
        }
    }
}

// ---------------- msg: register-resident q, chunked edge prefetch -----------
__global__ __launch_bounds__(128) void msg_kernel(const float* __restrict__ node,
                                                  const float* __restrict__ b2,
                                                  const int* __restrict__ dst) {
    __shared__ __align__(16) __half q_h[128 * QSLOT];   // 18.4 KB
    __shared__ float x_s[64];
    __shared__ float bb_s[64];
    __shared__ int e_s[32];
    __shared__ int d_s[32];
    int n = blockIdx.x;
    int t = threadIdx.x;

    int beg = g_off[n], end = g_off[n + 1];
    if (beg == end) return;

    const uint4* qn = reinterpret_cast<const uint4*>(g_q + (size_t)n * QC);
    uint32_t qbase = smem_to_u32(q_h);
#pragma unroll
    for (int i = 0; i < 8; i++) {
        int j = t + i * 128;
        uint32_t dstb = qbase + (uint32_t)((j >> 3) * (QSLOT * 2) + (j & 7) * 16);
        cp16a(dstb, qn + j);
    }
    asm volatile("cp.async.commit_group;");
    if (t < 64) x_s[t] = node[n * 64 + t];
    asm volatile("cp.async.wait_group 0;");
    __syncthreads();

    if (t < 64) {
        float bb = 0.f;
#pragma unroll 8
        for (int h = 0; h < 64; h++) bb = fmaf(x_s[h], b2[h * 64 + t], bb);
        bb_s[t] = bb;
    }

    float qf[64];
    {
        const uint4* myq = reinterpret_cast<const uint4*>(q_h + t * QSLOT);
#pragma unroll
        for (int i = 0; i < 8; i++) {
            uint4 v = myq[i];
            const __half2* h2 = reinterpret_cast<const __half2*>(&v);
#pragma unroll
            for (int p = 0; p < 4; p++) {
                float2 f = __half22float2(h2[p]);
                qf[i * 8 + p * 2] = f.x;
                qf[i * 8 + p * 2 + 1] = f.y;
            }
        }
    }
    __syncthreads();

    int k = t >> 1, half = t & 1;
    float mybb = bb_s[k];

    for (int cb = beg; cb < end; cb += 32) {
        int cnt = end - cb;
        if (cnt > 32) cnt = 32;
        __syncthreads();
        if (t < cnt) {
            int e = g_elist[cb + t];
            e_s[t] = e;
            d_s[t] = dst[e];
        }
        __syncthreads();
        for (int ii = 0; ii < cnt; ii++) {
            int e = e_s[ii];
            const float4* ep = reinterpret_cast<const float4*>(g_eh + (size_t)e * EHD) + half * 16;
            float acc = 0.f;
#pragma unroll
            for (int g = 0; g < 16; g++) {
                float4 ev = ep[g];
                acc = fmaf(ev.x, qf[g * 4 + 0], acc);
                acc = fmaf(ev.y, qf[g * 4 + 1], acc);
                acc = fmaf(ev.z, qf[g * 4 + 2], acc);
                acc = fmaf(ev.w, qf[g * 4 + 3], acc);
            }
            acc += __shfl_xor_sync(0xffffffffu, acc, 1);
            if (half == 0)
                atomicAdd(&g_agg[d_s[ii] * 64 + k], acc + mybb);
        }
    }
}

// ---------------- relu(agg) -> GRU -> LayerNorm ----------------
__global__ __launch_bounds__(256) void gru_ln_kernel(const float* __restrict__ hidden,
                                                     const float* __restrict__ bih,
                                                     const float* __restrict__ bhh,
                                                     const float* __restrict__ gamma,
                                                     const float* __restrict__ beta,
                                                     float* __restrict__ out) {
    __shared__ float xs[4][64], hs[4][64];
    __shared__ float redA[8], redB[8];
    int t = threadIdx.x;
    int sub = t >> 6, k = t & 63;
    int wid = t >> 5, lane = t & 31;
    float bi0 = bih[k], bi1 = bih[64 + k], bi2 = bih[128 + k];
    float bh0 = bhh[k], bh1 = bhh[64 + k], bh2 = bhh[128 + k];
    float gm = gamma[k], bt = beta[k];

    for (int n0 = blockIdx.x * 4; n0 < NN; n0 += gridDim.x * 4) {
        int n = n0 + sub;
        float x = fmaxf(g_agg[n * 64 + k], 0.f);
        float hv = hidden[n * 64 + k];
        xs[sub][k] = x;
        hs[sub][k] = hv;
        __syncthreads();
        float gi0 = bi0, gi1 = bi1, gi2 = bi2;
        float gh0 = bh0, gh1 = bh1, gh2 = bh2;
#pragma unroll 8
        for (int h = 0; h < 64; h++) {
            float xv = xs[sub][h], hh = hs[sub][h];
            const float* wi = &g_WihT[h * 192];
            const float* wh = &g_WhhT[h * 192];
            gi0 = fmaf(xv, wi[k], gi0);
            gi1 = fmaf(xv, wi[64 + k], gi1);
            gi2 = fmaf(xv, wi[128 + k], gi2);
            gh0 = fmaf(hh, wh[k], gh0);
            gh1 = fmaf(hh, wh[64 + k], gh1);
            gh2 = fmaf(hh, wh[128 + k], gh2);
        }
        float r = 1.f / (1.f + expf(-(gi0 + gh0)));
        float z = 1.f / (1.f + expf(-(gi1 + gh1)));
        float nn2 = tanhf(gi2 + r * gh2);
        float o = (1.f - z) * nn2 + z * hv;

        float s1 = o, s2 = o * o;
#pragma unroll
        for (int d = 16; d > 0; d >>= 1) {
            s1 += __shfl_xor_sync(0xffffffffu, s1, d);
            s2 += __shfl_xor_sync(0xffffffffu, s2, d);
        }
        if (lane == 0) { redA[wid] = s1; redB[wid] = s2; }
        __syncthreads();
        float S1 = redA[sub * 2] + redA[sub * 2 + 1];
        float S2 = redB[sub * 2] + redB[sub * 2 + 1];
        float mu = S1 * 0.015625f;
        float var = S2 * 0.015625f - mu * mu;
        out[n * 64 + k] = (o - mu) * rsqrtf(var + 1e-5f) * gm + bt;
        __syncthreads();
    }
}

// ---------------- launch (stream-parallel DAG, graph-capture fork/join) -----
extern "C" void kernel_launch(void* const* d_in, const int* in_sizes, int n_in,
                              void* d_out, int out_size) {
    const float* node   = (const float*)d_in[0];
    const float* edge   = (const float*)d_in[1];
    const float* hidden = (const float*)d_in[2];
    const int*   src    = (const int*)d_in[3];
    const int*   dst    = (const int*)d_in[4];
    const float* W1     = (const float*)d_in[5];
    const float* b1     = (const float*)d_in[6];
    const float* W2     = (const float*)d_in[7];
    const float* b2     = (const float*)d_in[8];
    const float* Wih    = (const float*)d_in[9];
    const float* Whh    = (const float*)d_in[10];
    const float* bih    = (const float*)d_in[11];
    const float* bhh    = (const float*)d_in[12];
    const float* gamma  = (const float*)d_in[13];
    const float* beta   = (const float*)d_in[14];
    float* out = (float*)d_out;

    const int QSMEM = 4 * 128 * STR2 * 2;    // 73728 B
    const int ESMEM = 2 * 128 * STRQ * 2;    // 102400 B

    static cudaStream_t s2 = nullptr, s3 = nullptr;
    static cudaEvent_t evRoot = nullptr, evPrep = nullptr, evE = nullptr, evC = nullptr;
    if (!s2) {
        cudaStreamCreateWithFlags(&s2, cudaStreamNonBlocking);
        cudaStreamCreateWithFlags(&s3, cudaStreamNonBlocking);
        cudaEventCreateWithFlags(&evRoot, cudaEventDisableTiming);
        cudaEventCreateWithFlags(&evPrep, cudaEventDisableTiming);
        cudaEventCreateWithFlags(&evE, cudaEventDisableTiming);
        cudaEventCreateWithFlags(&evC, cudaEventDisableTiming);
        cudaFuncSetAttribute(q_mma, cudaFuncAttributeMaxDynamicSharedMemorySize, QSMEM);
        cudaFuncSetAttribute(eh_mma, cudaFuncAttributeMaxDynamicSharedMemorySize, ESMEM);
    }

    // fork CSR chain onto s3 (independent of prep)
    cudaEventRecord(evRoot, 0);
    cudaStreamWaitEvent(s3, evRoot, 0);
    zero_cnt_kernel<<<(NN + 255) / 256, 256, 0, s3>>>();            // launch 1
    count_kernel<<<(NE + 255) / 256, 256, 0, s3>>>(src);            // 2

    // main stream: prep -> q_mma
    prep_kernel<<<64 + 512, 256>>>(node, edge, W1, W2, Wih, Whh);   // 3
    cudaEventRecord(evPrep, 0);
    q_mma<<<dim3(QC / 128, NNP / 128), 128, QSMEM>>>();             // 4 <- profiled

    // eh on s2 after prep
    cudaStreamWaitEvent(s2, evPrep, 0);
    eh_mma<<<NEP / 128, 256, ESMEM, s2>>>(b1);                      // 5

    // finish CSR on s3
    scan_kernel<<<1, 1024, 0, s3>>>();                              // 6
    scatter_kernel<<<(NE + 255) / 256, 256, 0, s3>>>(src);          // 7

    // join: msg needs q (s0), eh (s2), CSR (s3), agg-zero (prep, s0)
    cudaEventRecord(evE, s2);
    cudaEventRecord(evC, s3);
    cudaStreamWaitEvent(0, evE, 0);
    cudaStreamWaitEvent(0, evC, 0);
    msg_kernel<<<NN, 128>>>(node, b2, dst);                         // 8
    gru_ln_kernel<<<296, 256>>>(hidden, bih, bhh, gamma, beta, out);// 9
}